// round 10
// baseline (speedup 1.0000x reference)
#include <cuda_runtime.h>
#include <cuda_fp16.h>
#include <stdint.h>

#define NVERT 100000
#define NEDGE 20000
#define NPAIR 1600000
#define FD 128
#define HDIM 128
#define ECAP 192
#define VCAP 64
#define BN_EPS 1e-5f

// ---------------- scratch ----------------------------------------------------
__device__ __align__(16) __half g_h[(size_t)NVERT * HDIM];     // 25.6 MB (fp16)
__device__ __align__(16) __half g_Xe[(size_t)NEDGE * HDIM];    // 5.1 MB (fp16)
__device__ __align__(16) __half g_Wh[FD * HDIM];               // W^T in fp16 [n][k]
__device__ int   g_ecnt[NEDGE];
__device__ int   g_vcnt[NVERT];
__device__ int   g_ebucket[(size_t)NEDGE * ECAP];
__device__ int   g_vbucket[(size_t)NVERT * VCAP];
__device__ float g_colsum[HDIM];
__device__ float g_colsumsq[HDIM];

__device__ __forceinline__ uint32_t smem_u32(const void* p) {
    uint32_t a;
    asm("{ .reg .u64 t; cvta.to.shared.u64 t, %1; cvt.u32.u64 %0, t; }" : "=r"(a) : "l"(p));
    return a;
}
#define LDSM_X4(r0, r1, r2, r3, addr) \
    asm volatile("ldmatrix.sync.aligned.m8n8.x4.shared.b16 {%0,%1,%2,%3}, [%4];" \
                 : "=r"(r0), "=r"(r1), "=r"(r2), "=r"(r3) : "r"(addr))

// ---------------- prep: W transpose->fp16 + zero stats -----------------------
__global__ void prep_kernel(const float* __restrict__ W) {
    int idx = blockIdx.x * 256 + threadIdx.x;
    int k = idx >> 7, n = idx & 127;
    g_Wh[n * FD + k] = __float2half(W[idx]);
    if (blockIdx.x == 0 && threadIdx.x < 128) {
        g_colsum[threadIdx.x]   = 0.f;
        g_colsumsq[threadIdx.x] = 0.f;
    }
}

// ---------------- bucket build (4 pairs per thread) --------------------------
__global__ void fill_kernel(const int* __restrict__ vid, const int* __restrict__ eid) {
    int i = blockIdx.x * blockDim.x + threadIdx.x;
    if (i >= NPAIR / 4) return;
    int4 v4 = ((const int4*)vid)[i];
    int4 e4 = ((const int4*)eid)[i];
    int vv[4] = {v4.x, v4.y, v4.z, v4.w};
    int ee[4] = {e4.x, e4.y, e4.z, e4.w};
#pragma unroll
    for (int t = 0; t < 4; t++) {
        int a = atomicAdd(&g_ecnt[ee[t]], 1);
        if (a < ECAP) g_ebucket[(size_t)ee[t] * ECAP + a] = vv[t];
        int c = atomicAdd(&g_vcnt[vv[t]], 1);
        if (c < VCAP) g_vbucket[(size_t)vv[t] * VCAP + c] = ee[t];
    }
}

// ---------------- fp16 HMMA GEMM (64x128 tile, ldmatrix) + fused stats -------
// 256 threads = 8 warps: warp = (rowgroup rg 0..3) x (n-half nh 0..1)
#define LDH 136
#define SM_XS   0                      // 64*136*2   = 17408
#define SM_WS   17408                  // 128*136*2  = 34816
#define SM_SS   52224                  // 4*128*4    = 2048
#define SM_SQ   54272                  // 2048
#define SM_BIAS 56320                  // 512
#define SM_TOTAL 56832

__global__ void __launch_bounds__(256, 4) gemm_mma_kernel(const float* __restrict__ X,
                                                          const float* __restrict__ bias) {
    extern __shared__ char smem[];
    __half* Xs  = (__half*)(smem + SM_XS);
    __half* Ws  = (__half*)(smem + SM_WS);
    float*  ss  = (float*)(smem + SM_SS);
    float*  sq  = (float*)(smem + SM_SQ);
    float*  bsm = (float*)(smem + SM_BIAS);

    const int tid  = threadIdx.x;
    const int wid  = tid >> 5;
    const int lane = tid & 31;
    const int rg   = wid >> 1;        // row group 0..3
    const int nh   = wid & 1;         // n half 0..1
    const int m0   = blockIdx.x * 64;

    if (tid < 32) ((float4*)bsm)[tid] = ((const float4*)bias)[tid];

    // W fp16 [n][k] -> smem (full 128x128)
    {
        const __half2* __restrict__ Wh2 = (const __half2*)g_Wh;
#pragma unroll
        for (int i = 0; i < 32; i++) {
            int idx = tid + i * 256;
            int n = idx >> 6, k2 = idx & 63;
            *(__half2*)&Ws[n * LDH + k2 * 2] = Wh2[idx];
        }
    }
    // X tile (64 rows) fp32 -> fp16 smem
    {
        const float4* __restrict__ X4 = (const float4*)X;
#pragma unroll
        for (int i = 0; i < 8; i++) {
            int idx = tid + i * 256;          // 2048 float4
            int row = idx >> 5, c4 = idx & 31;
            int gr = m0 + row;
            float4 v = make_float4(0.f, 0.f, 0.f, 0.f);
            if (gr < NVERT) v = X4[(size_t)gr * 32 + c4];
            __half2 p0 = __floats2half2_rn(v.x, v.y);
            __half2 p1 = __floats2half2_rn(v.z, v.w);
            uint2 pk;
            pk.x = *(uint32_t*)&p0; pk.y = *(uint32_t*)&p1;
            *(uint2*)&Xs[row * LDH + c4 * 4] = pk;
        }
    }
    __syncthreads();

    const int g   = lane >> 2;
    const int tig = lane & 3;

    float d[8][4];
#pragma unroll
    for (int t = 0; t < 8; t++)
#pragma unroll
        for (int j = 0; j < 4; j++) d[t][j] = 0.f;

    const uint32_t sbase = smem_u32(smem);
    // A ldmatrix lane address: row = rg*16 + (lane&15), col = (lane>>4)*8
    const int arow = rg * 16 + (lane & 15);
    const uint32_t a_addr0 = sbase + SM_XS + (uint32_t)(arow * LDH + ((lane >> 4) << 3)) * 2;
    // B ldmatrix lane address: row = nh*64 + (lane&7) + (lane&16 ? 8 : 0),
    //                          col = ((lane>>3)&1)*8
    const int brow = nh * 64 + (lane & 7) + ((lane & 16) ? 8 : 0);
    const uint32_t b_addr0 = sbase + SM_WS + (uint32_t)(brow * LDH + (((lane >> 3) & 1) << 3)) * 2;

#pragma unroll
    for (int kk = 0; kk < 8; kk++) {
        uint32_t a0, a1, a2, a3;
        LDSM_X4(a0, a1, a2, a3, a_addr0 + kk * 32);
#pragma unroll
        for (int nt = 0; nt < 4; nt++) {     // each x4 covers 2 n-tiles
            uint32_t b0, b1, b2, b3;
            LDSM_X4(b0, b1, b2, b3, b_addr0 + nt * (16 * LDH * 2) + kk * 32);
            asm volatile(
                "mma.sync.aligned.m16n8k16.row.col.f32.f16.f16.f32 "
                "{%0,%1,%2,%3},{%4,%5,%6,%7},{%8,%9},{%0,%1,%2,%3};"
                : "+f"(d[2*nt][0]), "+f"(d[2*nt][1]), "+f"(d[2*nt][2]), "+f"(d[2*nt][3])
                : "r"(a0), "r"(a1), "r"(a2), "r"(a3), "r"(b0), "r"(b1));
            asm volatile(
                "mma.sync.aligned.m16n8k16.row.col.f32.f16.f16.f32 "
                "{%0,%1,%2,%3},{%4,%5,%6,%7},{%8,%9},{%0,%1,%2,%3};"
                : "+f"(d[2*nt+1][0]), "+f"(d[2*nt+1][1]), "+f"(d[2*nt+1][2]), "+f"(d[2*nt+1][3])
                : "r"(a0), "r"(a1), "r"(a2), "r"(a3), "r"(b2), "r"(b3));
        }
    }

    const int gr0 = m0 + rg * 16 + g;
    const int gr1 = gr0 + 8;
    const bool ok0 = gr0 < NVERT;
    const bool ok1 = gr1 < NVERT;

#pragma unroll
    for (int t = 0; t < 8; t++) {
        const int c = nh * 64 + t * 8 + tig * 2;
        float b0f = bsm[c], b1f = bsm[c + 1];
        float v0 = d[t][0] + b0f, v1 = d[t][1] + b1f;
        float v2 = d[t][2] + b0f, v3 = d[t][3] + b1f;
        if (ok0) *(__half2*)&g_h[(size_t)gr0 * HDIM + c] = __floats2half2_rn(v0, v1);
        if (ok1) *(__half2*)&g_h[(size_t)gr1 * HDIM + c] = __floats2half2_rn(v2, v3);

        float s0 = (ok0 ? v0 : 0.f) + (ok1 ? v2 : 0.f);
        float s1 = (ok0 ? v1 : 0.f) + (ok1 ? v3 : 0.f);
        float q0 = (ok0 ? v0 * v0 : 0.f) + (ok1 ? v2 * v2 : 0.f);
        float q1 = (ok0 ? v1 * v1 : 0.f) + (ok1 ? v3 * v3 : 0.f);
#pragma unroll
        for (int m = 4; m <= 16; m <<= 1) {
            s0 += __shfl_xor_sync(0xffffffffu, s0, m);
            s1 += __shfl_xor_sync(0xffffffffu, s1, m);
            q0 += __shfl_xor_sync(0xffffffffu, q0, m);
            q1 += __shfl_xor_sync(0xffffffffu, q1, m);
        }
        if (g == 0) {
            ss[rg * 128 + c] = s0; ss[rg * 128 + c + 1] = s1;
            sq[rg * 128 + c] = q0; sq[rg * 128 + c + 1] = q1;
        }
    }
    __syncthreads();

    if (tid < 128) {
        float t = ss[tid] + ss[128 + tid] + ss[256 + tid] + ss[384 + tid];
        atomicAdd(&g_colsum[tid], t);
    } else {
        int c = tid - 128;
        float t = sq[c] + sq[128 + c] + sq[256 + c] + sq[384 + c];
        atomicAdd(&g_colsumsq[c], t);
    }
}

// ------ batched gather accumulate: 4 independent LDG.128 in flight -----------
#define ACC_PK(pk) do { \
    float2 f0 = __half22float2(*(__half2*)&(pk).x); \
    float2 f1 = __half22float2(*(__half2*)&(pk).y); \
    float2 f2 = __half22float2(*(__half2*)&(pk).z); \
    float2 f3 = __half22float2(*(__half2*)&(pk).w); \
    acc[0] += f0.x; acc[1] += f0.y; acc[2] += f1.x; acc[3] += f1.y; \
    acc[4] += f2.x; acc[5] += f2.y; acc[6] += f3.x; acc[7] += f3.y; \
} while (0)

__device__ __forceinline__ void gather_rows(const uint4* __restrict__ base, int rowstride16,
                                            const int* __restrict__ bucket, int n,
                                            int lane, int half, int sub, float* acc) {
    for (int j0 = 0; j0 < n; j0 += 32) {
        int my = (j0 + lane < n) ? bucket[j0 + lane] : 0;
        int nthis = min(32, n - j0);
        for (int t = 0; t < nthis; t += 8) {
            int i0 = t + half, i1 = t + 2 + half, i2 = t + 4 + half, i3 = t + 6 + half;
            int v0 = __shfl_sync(0xffffffffu, my, i0);
            int v1 = __shfl_sync(0xffffffffu, my, i1);
            int v2 = __shfl_sync(0xffffffffu, my, i2);
            int v3 = __shfl_sync(0xffffffffu, my, i3);
            uint4 p0 = __ldg(&base[(size_t)v0 * rowstride16 + sub]);
            uint4 p1 = __ldg(&base[(size_t)v1 * rowstride16 + sub]);
            uint4 p2 = __ldg(&base[(size_t)v2 * rowstride16 + sub]);
            uint4 p3 = __ldg(&base[(size_t)v3 * rowstride16 + sub]);
            if (i0 < nthis) ACC_PK(p0);
            if (i1 < nthis) ACC_PK(p1);
            if (i2 < nthis) ACC_PK(p2);
            if (i3 < nthis) ACC_PK(p3);
        }
    }
#pragma unroll
    for (int u = 0; u < 8; u++)
        acc[u] += __shfl_down_sync(0xffffffffu, acc[u], 16);
}

// ---------------- phase 1: edge means (BN finalize fused) --------------------
__global__ void __launch_bounds__(256, 6) edge_agg_kernel(const float* __restrict__ gamma,
                                                          const float* __restrict__ beta) {
    __shared__ float s_scale[128], s_shift[128];
    const int tid = threadIdx.x;
    if (tid < 128) {
        float mu  = g_colsum[tid] * (1.0f / NVERT);
        float var = g_colsumsq[tid] * (1.0f / NVERT) - mu * mu;
        float sc  = gamma[tid] * rsqrtf(var + BN_EPS);
        s_scale[tid] = sc;
        s_shift[tid] = beta[tid] - mu * sc;
    }
    __syncthreads();

    int w    = (blockIdx.x * blockDim.x + tid) >> 5;
    int lane = tid & 31;
    if (w >= NEDGE) return;

    int cnt = g_ecnt[w];
    int n   = min(cnt, ECAP);
    const int half = lane >> 4;
    const int sub  = lane & 15;

    float acc[8] = {0.f, 0.f, 0.f, 0.f, 0.f, 0.f, 0.f, 0.f};
    gather_rows((const uint4*)g_h, 16, &g_ebucket[(size_t)w * ECAP], n, lane, half, sub, acc);

    if (lane < 16) {
        uint4 opk; opk.x = opk.y = opk.z = opk.w = 0u;
        if (cnt > 0) {
            float inv = 1.0f / (float)cnt;
            float4 sc0 = ((const float4*)s_scale)[sub * 2];
            float4 sc1 = ((const float4*)s_scale)[sub * 2 + 1];
            float4 sh0 = ((const float4*)s_shift)[sub * 2];
            float4 sh1 = ((const float4*)s_shift)[sub * 2 + 1];
            __half2 p0 = __floats2half2_rn(fmaf(acc[0] * inv, sc0.x, sh0.x), fmaf(acc[1] * inv, sc0.y, sh0.y));
            __half2 p1 = __floats2half2_rn(fmaf(acc[2] * inv, sc0.z, sh0.z), fmaf(acc[3] * inv, sc0.w, sh0.w));
            __half2 p2 = __floats2half2_rn(fmaf(acc[4] * inv, sc1.x, sh1.x), fmaf(acc[5] * inv, sc1.y, sh1.y));
            __half2 p3 = __floats2half2_rn(fmaf(acc[6] * inv, sc1.z, sh1.z), fmaf(acc[7] * inv, sc1.w, sh1.w));
            opk.x = *(uint32_t*)&p0; opk.y = *(uint32_t*)&p1;
            opk.z = *(uint32_t*)&p2; opk.w = *(uint32_t*)&p3;
        }
        ((uint4*)g_Xe)[(size_t)w * 16 + sub] = opk;
    }
}

// ---------------- phase 2: vertex means + ReLU -------------------------------
__global__ void __launch_bounds__(256, 6) vert_agg_kernel(float* __restrict__ out) {
    int w    = (blockIdx.x * blockDim.x + threadIdx.x) >> 5;
    int lane = threadIdx.x & 31;
    if (w >= NVERT) return;

    int cnt = g_vcnt[w];
    int n   = min(cnt, VCAP);
    const int half = lane >> 4;
    const int sub  = lane & 15;

    float acc[8] = {0.f, 0.f, 0.f, 0.f, 0.f, 0.f, 0.f, 0.f};
    gather_rows((const uint4*)g_Xe, 16, &g_vbucket[(size_t)w * VCAP], n, lane, half, sub, acc);

    if (lane < 16) {
        float inv = (cnt > 0) ? 1.0f / (float)cnt : 0.0f;
        float4 o0, o1;
        o0.x = fmaxf(acc[0] * inv, 0.f); o0.y = fmaxf(acc[1] * inv, 0.f);
        o0.z = fmaxf(acc[2] * inv, 0.f); o0.w = fmaxf(acc[3] * inv, 0.f);
        o1.x = fmaxf(acc[4] * inv, 0.f); o1.y = fmaxf(acc[5] * inv, 0.f);
        o1.z = fmaxf(acc[6] * inv, 0.f); o1.w = fmaxf(acc[7] * inv, 0.f);
        ((float4*)out)[(size_t)w * 32 + sub * 2]     = o0;
        ((float4*)out)[(size_t)w * 32 + sub * 2 + 1] = o1;
    }
}

// ---------------- launcher ----------------------------------------------------
extern "C" void kernel_launch(void* const* d_in, const int* in_sizes, int n_in,
                              void* d_out, int out_size) {
    const float* X     = (const float*)d_in[0];
    const int*   vid   = (const int*)d_in[1];
    const int*   eid   = (const int*)d_in[2];
    const float* W     = (const float*)d_in[3];
    const float* bias  = (const float*)d_in[4];
    const float* gamma = (const float*)d_in[5];
    const float* beta  = (const float*)d_in[6];
    float*       out   = (float*)d_out;

    static cudaStream_t sB = nullptr;
    static cudaEvent_t evFork = nullptr, evJoin = nullptr;
    if (sB == nullptr) {
        cudaStreamCreateWithFlags(&sB, cudaStreamNonBlocking);
        cudaEventCreateWithFlags(&evFork, cudaEventDisableTiming);
        cudaEventCreateWithFlags(&evJoin, cudaEventDisableTiming);
        cudaFuncSetAttribute(gemm_mma_kernel, cudaFuncAttributeMaxDynamicSharedMemorySize, SM_TOTAL);
    }

    void *p_ecnt, *p_vcnt;
    cudaGetSymbolAddress(&p_ecnt, g_ecnt);
    cudaGetSymbolAddress(&p_vcnt, g_vcnt);

    cudaEventRecord(evFork, 0);
    cudaStreamWaitEvent(sB, evFork, 0);
    cudaMemsetAsync(p_ecnt, 0, NEDGE * sizeof(int), sB);
    cudaMemsetAsync(p_vcnt, 0, NVERT * sizeof(int), sB);
    fill_kernel<<<(NPAIR / 4 + 255) / 256, 256, 0, sB>>>(vid, eid);
    cudaEventRecord(evJoin, sB);

    prep_kernel<<<64, 256>>>(W);
    gemm_mma_kernel<<<(NVERT + 63) / 64, 256, SM_TOTAL>>>(X, bias);

    cudaStreamWaitEvent(0, evJoin, 0);
    edge_agg_kernel<<<(NEDGE * 32 + 255) / 256, 256>>>(gamma, beta);
    vert_agg_kernel<<<(NVERT * 32 + 255) / 256, 256>>>(out);
}